// round 2
// baseline (speedup 1.0000x reference)
#include <cuda_runtime.h>
#include <stdint.h>

// ---------------- problem constants ----------------
#define NVAR 4
#define BATCH 32
#define NIN 32
#define NOUT 32
#define NFEAT 32
#define TSTEPS 256
#define KLANES 1024          // NOUT * NFEAT

static __device__ float g_w1[NVAR * 33 * NOUT];            // thn1/den, m=0..32 (32 = ones row)
static __device__ float g_w2[NVAR * 1057 * NOUT];          // reordered thn2/den: [0..31]=a1 ch, [32..1055]=y2 k, [1056]=bias
static __device__ float g_a1s[NOUT * NVAR * TSTEPS * BATCH];   // [c][n][t][b]
static __device__ float g_beta1[KLANES * NVAR * TSTEPS];       // [k][n][t]
static __device__ float g_beta2[KLANES * NVAR * TSTEPS];
static __device__ float g_y2[NVAR * TSTEPS * KLANES * BATCH];  // [n][t][k][b]  (128 MiB)
static __device__ unsigned g_keys[20];

// ---------------- threefry2x32-20 (JAX-compatible) ----------------
__device__ __forceinline__ void tf2x32(unsigned k0, unsigned k1,
                                       unsigned x0, unsigned x1,
                                       unsigned& o0, unsigned& o1) {
    unsigned ks2 = k0 ^ k1 ^ 0x1BD11BDAu;
    x0 += k0; x1 += k1;
#define TFR(r) { x0 += x1; x1 = (x1 << (r)) | (x1 >> (32 - (r))); x1 ^= x0; }
    TFR(13) TFR(15) TFR(26) TFR(6)
    x0 += k1; x1 += ks2 + 1u;
    TFR(17) TFR(29) TFR(16) TFR(24)
    x0 += ks2; x1 += k0 + 2u;
    TFR(13) TFR(15) TFR(26) TFR(6)
    x0 += k0; x1 += k1 + 3u;
    TFR(17) TFR(29) TFR(16) TFR(24)
    x0 += k1; x1 += ks2 + 4u;
    TFR(13) TFR(15) TFR(26) TFR(6)
    x0 += ks2; x1 += k0 + 5u;
#undef TFR
    o0 = x0; o1 = x1;
}

// partitionable-mode random_bits(32): counter = (hi=0, lo=i), bits = out0 ^ out1
__device__ __forceinline__ float tf_uniform(unsigned k0, unsigned k1, unsigned ctr) {
    unsigned o0, o1;
    tf2x32(k0, k1, 0u, ctr, o0, o1);
    unsigned bits = o0 ^ o1;
    return __uint_as_float((bits >> 9) | 0x3f800000u) - 1.0f;
}

__device__ __forceinline__ float sigmoidf_(float x) {
    return 1.0f / (1.0f + expf(-x));
}

__device__ __forceinline__ float theta_eff(float t) {
    t = fminf(fmaxf(t, -10.0f), 10.0f);
    if (fabsf(t) < 0.01f) t = 0.0f;
    return t;
}

// ---------------- kernel 0: derive keys ----------------
// root = key(42) = (0,42). split(root,4) fold-like: child_i = threefry(root,(0,i)) raw pair.
// k1 -> pmac1 noise ; k2 -> bank1 ; k3 -> bank2 ; k4 -> pmac2 noise
// bank split: kR,kC,kmu,k0 = threefry(bank_key,(0,0..3))
__global__ void k_keys() {
    unsigned ck[8];
    for (int i = 0; i < 4; i++) {
        unsigned o0, o1;
        tf2x32(0u, 42u, 0u, (unsigned)i, o0, o1);
        ck[2 * i] = o0; ck[2 * i + 1] = o1;
    }
    g_keys[0] = ck[0]; g_keys[1] = ck[1];   // k1
    g_keys[2] = ck[6]; g_keys[3] = ck[7];   // k4
    for (int bank = 0; bank < 2; bank++) {
        unsigned b0 = ck[2 + 2 * bank], b1 = ck[3 + 2 * bank];  // k2 / k3
        for (int j = 0; j < 4; j++) {
            unsigned o0, o1;
            tf2x32(b0, b1, 0u, (unsigned)j, o0, o1);
            g_keys[4 + bank * 8 + 2 * j] = o0;
            g_keys[4 + bank * 8 + 2 * j + 1] = o1;
        }
    }
}

// ---------------- kernel 1: weights for pmac1 ----------------
// block = (n,o) : 128 blocks x 64 threads, m = tid (0..33)
__global__ void k_prep_w1(const float* __restrict__ theta1) {
    __shared__ float sh[64];
    int n = blockIdx.x >> 5, o = blockIdx.x & 31;
    int m = threadIdx.x;
    unsigned nk0 = g_keys[0], nk1 = g_keys[1];
    float thn = 0.0f, av = 0.0f;
    if (m < 34) {
        float th = theta_eff(theta1[m * 32 + o]);
        float u = tf_uniform(nk0, nk1, (unsigned)((n * 34 + m) * 32 + o));
        float noise = (u * 2.0f - 1.0f) * 0.05f + 1.0f;
        thn = th * noise;
        av = fabsf(thn);
    }
    sh[threadIdx.x] = av;
    __syncthreads();
    if (threadIdx.x == 0) {
        float s = 0.0f;
        for (int i = 0; i < 64; i++) s += sh[i];
        sh[0] = s + 1e-10f;
    }
    __syncthreads();
    float den = sh[0];
    if (m < 33) g_w1[(n * 33 + m) * 32 + o] = thn / den;
}

// ---------------- kernel 2: weights for pmac2 (reordered) ----------------
// block = (n,o): 128 blocks x 128 threads. two passes over m=0..1057.
__global__ void k_prep_w2(const float* __restrict__ theta2) {
    __shared__ float sh[128];
    int n = blockIdx.x >> 5, o = blockIdx.x & 31;
    int tid = threadIdx.x;
    unsigned nk0 = g_keys[2], nk1 = g_keys[3];
    float part = 0.0f;
    for (int m = tid; m < 1058; m += 128) {
        float th = theta_eff(theta2[m * 32 + o]);
        float u = tf_uniform(nk0, nk1, (unsigned)((n * 1058 + m) * 32 + o));
        float noise = (u * 2.0f - 1.0f) * 0.05f + 1.0f;
        part += fabsf(th * noise);
    }
    sh[tid] = part;
    __syncthreads();
    for (int s = 64; s > 0; s >>= 1) {
        if (tid < s) sh[tid] += sh[tid + s];
        __syncthreads();
    }
    float den = sh[0] + 1e-10f;
    for (int m = tid; m < 1057; m += 128) {   // m=1057 (zeros row) excluded from numerator
        float th = theta_eff(theta2[m * 32 + o]);
        float u = tf_uniform(nk0, nk1, (unsigned)((n * 1058 + m) * 32 + o));
        float noise = (u * 2.0f - 1.0f) * 0.05f + 1.0f;
        float w = (th * noise) / den;
        int mm;
        if (m == 1056) mm = 1056;               // ones/bias row
        else {
            int c = m / 33, r = m % 33;
            mm = (r == 0) ? c : (32 + c * 32 + (r - 1));
        }
        g_w2[(n * 1057 + mm) * 32 + o] = w;
    }
}

// ---------------- kernel 3: pmac1 -> a1s[c][n][t][b] ----------------
// block = (n,b): 128 blocks x 256 threads (t)
__global__ void __launch_bounds__(256) k_pmac1(const float* __restrict__ x) {
    __shared__ float w[33 * 32];
    int n = blockIdx.x >> 5, b = blockIdx.x & 31;
    int t = threadIdx.x;
    for (int i = threadIdx.x; i < 33 * 32; i += 256) w[i] = g_w1[n * (33 * 32) + i];
    __syncthreads();
    float z[32];
#pragma unroll
    for (int o = 0; o < 32; o++) z[o] = w[32 * 32 + o];   // ones-row term
    const float* xp = x + ((n * 32 + b) * 32) * 256 + t;
#pragma unroll 4
    for (int m = 0; m < 32; m++) {
        float xv = xp[m * 256];
#pragma unroll
        for (int o = 0; o < 32; o++) z[o] = fmaf(xv, w[m * 32 + o], z[o]);
    }
#pragma unroll
    for (int o = 0; o < 32; o++) {
        float a = 0.05f + 0.5f * tanhf((z[o] - 0.3f) * 3.0f);
        g_a1s[((o * 4 + n) * 256 + t) * 32 + b] = a;
    }
}

// ---------------- kernel 4: beta tables ----------------
// grid (4096, 2): y = bank. thread -> (k,n,t), write [k][n][t]
__global__ void __launch_bounds__(256) k_beta(const float* __restrict__ Rlf,
                                              const float* __restrict__ Clf) {
    int bank = blockIdx.y;
    int gid = blockIdx.x * 256 + threadIdx.x;     // 0 .. 1048575
    int t = gid & 255;
    int n = (gid >> 8) & 3;
    int k = gid >> 10;
    int off = 4 + bank * 8;
    unsigned kR0 = g_keys[off + 0], kR1 = g_keys[off + 1];
    unsigned kC0 = g_keys[off + 2], kC1 = g_keys[off + 3];
    unsigned km0 = g_keys[off + 4], km1 = g_keys[off + 5];
    unsigned ctr = (unsigned)(((t * 1024) + k) * 4 + n);   // iota over (T,K,N,1)
    float nR = (tf_uniform(kR0, kR1, ctr) * 2.0f - 1.0f) * 0.05f + 1.0f;
    float nC = (tf_uniform(kC0, kC1, ctr) * 2.0f - 1.0f) * 0.05f + 1.0f;
    float mu = tf_uniform(km0, km1, ctr) * 0.2f + 1.0f;
    float R_ = Rlf[k * 2 + bank];
    float C_ = Clf[k * 2 + bank];
    float Rt = sigmoidf_(R_) * (1e7f - 1e5f) + 1e5f;
    float Ct = sigmoidf_(C_) * (1e-4f - 1e-7f) + 1e-7f;
    float RC = mu * (Rt * nR) * (Ct * nC);
    float beta = RC / (RC + 0.1f);
    float* dst = bank ? g_beta2 : g_beta1;
    dst[(k * 4 + n) * 256 + t] = beta;
}

// ---------------- kernel 5: fused double filter-bank scan ----------------
// thread = (k,n,b): 512 blocks x 256. outs[t] = state BEFORE consuming x[t].
__global__ void __launch_bounds__(256) k_scan() {
    int g = blockIdx.x * 256 + threadIdx.x;
    int b = g & 31;
    int n = (g >> 5) & 3;
    int k = g >> 7;
    unsigned s10 = g_keys[10], s11 = g_keys[11];   // bank1 k0
    unsigned s20 = g_keys[18], s21 = g_keys[19];   // bank2 k0
    unsigned sctr = (unsigned)((k * 4 + n) * 32 + b);
    float s1 = tf_uniform(s10, s11, sctr);
    float s2 = tf_uniform(s20, s21, sctr);
    const float* b1p = g_beta1 + (k * 4 + n) * 256;
    const float* b2p = g_beta2 + (k * 4 + n) * 256;
    const float* xp = g_a1s + (((k >> 5) * 4 + n) * 256) * 32 + b;
    float* yp = g_y2 + (n * 256 * 1024 + k) * 32 + b;
#pragma unroll 4
    for (int t = 0; t < 256; t++) {
        float b1 = b1p[t];
        float b2 = b2p[t];
        float xv = xp[t * 32];
        float y1 = s1;                         // bank1 output at t (pre-update)
        s1 = b1 * s1 + (1.0f - b1) * xv;
        yp[t * 32768] = s2;                    // bank2 output at t (pre-update)
        s2 = b2 * s2 + (1.0f - b2) * y1;
    }
}

// ---------------- kernel 6: pmac2 GEMM + activation + final layout ----------------
// block = (n, t-chunk of 8): 128 blocks x 256 threads
// thread: o-quad = (tid&7)*4, b-oct = ((tid>>3)&3)*8, t = t0 + (tid>>5)
__global__ void __launch_bounds__(256) k_pmac2(float* __restrict__ out) {
    __shared__ float f_s[16][8][32];
    __shared__ float w_s[16][32];
    int n = blockIdx.x >> 5;
    int t0 = (blockIdx.x & 31) * 8;
    int tid = threadIdx.x;
    int o4 = (tid & 7) * 4;
    int b8 = ((tid >> 3) & 3) * 8;
    int tq = tid >> 5;
    float acc[4][8];
#pragma unroll
    for (int oi = 0; oi < 4; oi++) {
        float bias = g_w2[(n * 1057 + 1056) * 32 + o4 + oi];
#pragma unroll
        for (int bi = 0; bi < 8; bi++) acc[oi][bi] = bias;
    }
    for (int m0 = 0; m0 < 1056; m0 += 16) {
        __syncthreads();
        for (int i = tid; i < 512; i += 256) {
            int j = i >> 5, o = i & 31;
            w_s[j][o] = g_w2[(n * 1057 + m0 + j) * 32 + o];
        }
        for (int l = tid; l < 1024; l += 256) {
            int j = l >> 6;
            int rem = l & 63;
            int tt = rem >> 3;
            int bq = (rem & 7) * 4;
            int mm = m0 + j;
            const float* src = (mm < 32)
                ? &g_a1s[((mm * 4 + n) * 256 + (t0 + tt)) * 32 + bq]
                : &g_y2[((n * 256 + t0 + tt) * 1024 + (mm - 32)) * 32 + bq];
            *(float4*)&f_s[j][tt][bq] = *(const float4*)src;
        }
        __syncthreads();
#pragma unroll
        for (int j = 0; j < 16; j++) {
            float4 fa = *(float4*)&f_s[j][tq][b8];
            float4 fb = *(float4*)&f_s[j][tq][b8 + 4];
            float fv[8] = {fa.x, fa.y, fa.z, fa.w, fb.x, fb.y, fb.z, fb.w};
#pragma unroll
            for (int oi = 0; oi < 4; oi++) {
                float wv = w_s[j][o4 + oi];
#pragma unroll
                for (int bi = 0; bi < 8; bi++)
                    acc[oi][bi] = fmaf(wv, fv[bi], acc[oi][bi]);
            }
        }
    }
#pragma unroll
    for (int oi = 0; oi < 4; oi++)
#pragma unroll
        for (int bi = 0; bi < 8; bi++) {
            float z = acc[oi][bi];
            float a = 0.05f + 0.5f * tanhf((z - 0.3f) * 3.0f);
            out[((n * 32 + (b8 + bi)) * 32 + (o4 + oi)) * 256 + (t0 + tq)] = a;
        }
}

// ---------------- launch ----------------
extern "C" void kernel_launch(void* const* d_in, const int* in_sizes, int n_in,
                              void* d_out, int out_size) {
    (void)in_sizes; (void)n_in; (void)out_size;
    const float* x      = (const float*)d_in[0];   // (4,32,32,256)
    const float* theta1 = (const float*)d_in[1];   // (34,32)
    const float* theta2 = (const float*)d_in[2];   // (1058,32)
    const float* Rlf    = (const float*)d_in[3];   // (32,32,2)
    const float* Clf    = (const float*)d_in[4];   // (32,32,2)
    float* out = (float*)d_out;

    k_keys<<<1, 1>>>();
    k_prep_w1<<<128, 64>>>(theta1);
    k_prep_w2<<<128, 128>>>(theta2);
    k_pmac1<<<128, 256>>>(x);
    k_beta<<<dim3(4096, 2), 256>>>(Rlf, Clf);
    k_scan<<<512, 256>>>();
    k_pmac2<<<128, 256>>>(out);
}

// round 3
// speedup vs baseline: 2.3159x; 2.3159x over previous
#include <cuda_runtime.h>
#include <stdint.h>

// ---------------- problem constants ----------------
#define NVAR 4
#define BATCH 32
#define TSTEPS 256
#define KLANES 1024          // NOUT * NFEAT

static __device__ float g_w1[NVAR * 33 * 32];              // thn1/den, m=0..32 (32 = ones row)
static __device__ float g_w2[NVAR * 1057 * 32];            // reordered: [0..31]=a1 ch, [32..1055]=y2 k, [1056]=bias
static __device__ float g_a1s[32 * NVAR * TSTEPS * BATCH]; // [c][n][t][b]
static __device__ float g_beta1[NVAR * TSTEPS * KLANES];   // [n][t][k]
static __device__ float g_beta2[NVAR * TSTEPS * KLANES];
static __device__ unsigned g_keys[20];

// ---------------- threefry2x32-20 (JAX-compatible) ----------------
__device__ __forceinline__ void tf2x32(unsigned k0, unsigned k1,
                                       unsigned x0, unsigned x1,
                                       unsigned& o0, unsigned& o1) {
    unsigned ks2 = k0 ^ k1 ^ 0x1BD11BDAu;
    x0 += k0; x1 += k1;
#define TFR(r) { x0 += x1; x1 = (x1 << (r)) | (x1 >> (32 - (r))); x1 ^= x0; }
    TFR(13) TFR(15) TFR(26) TFR(6)
    x0 += k1; x1 += ks2 + 1u;
    TFR(17) TFR(29) TFR(16) TFR(24)
    x0 += ks2; x1 += k0 + 2u;
    TFR(13) TFR(15) TFR(26) TFR(6)
    x0 += k0; x1 += k1 + 3u;
    TFR(17) TFR(29) TFR(16) TFR(24)
    x0 += k1; x1 += ks2 + 4u;
    TFR(13) TFR(15) TFR(26) TFR(6)
    x0 += ks2; x1 += k0 + 5u;
#undef TFR
    o0 = x0; o1 = x1;
}

// partitionable-mode random_bits(32): counter = (hi=0, lo=i), bits = out0 ^ out1
__device__ __forceinline__ float tf_uniform(unsigned k0, unsigned k1, unsigned ctr) {
    unsigned o0, o1;
    tf2x32(k0, k1, 0u, ctr, o0, o1);
    unsigned bits = o0 ^ o1;
    return __uint_as_float((bits >> 9) | 0x3f800000u) - 1.0f;
}

__device__ __forceinline__ float sigmoidf_(float x) {
    return 1.0f / (1.0f + expf(-x));
}

__device__ __forceinline__ float theta_eff(float t) {
    t = fminf(fmaxf(t, -10.0f), 10.0f);
    if (fabsf(t) < 0.01f) t = 0.0f;
    return t;
}

// ---------------- kernel 0: derive keys ----------------
__global__ void k_keys() {
    unsigned ck[8];
    for (int i = 0; i < 4; i++) {
        unsigned o0, o1;
        tf2x32(0u, 42u, 0u, (unsigned)i, o0, o1);
        ck[2 * i] = o0; ck[2 * i + 1] = o1;
    }
    g_keys[0] = ck[0]; g_keys[1] = ck[1];   // k1
    g_keys[2] = ck[6]; g_keys[3] = ck[7];   // k4
    for (int bank = 0; bank < 2; bank++) {
        unsigned b0 = ck[2 + 2 * bank], b1 = ck[3 + 2 * bank];  // k2 / k3
        for (int j = 0; j < 4; j++) {
            unsigned o0, o1;
            tf2x32(b0, b1, 0u, (unsigned)j, o0, o1);
            g_keys[4 + bank * 8 + 2 * j] = o0;
            g_keys[4 + bank * 8 + 2 * j + 1] = o1;
        }
    }
}

// ---------------- kernel 1: weights for pmac1 ----------------
__global__ void k_prep_w1(const float* __restrict__ theta1) {
    __shared__ float sh[64];
    int n = blockIdx.x >> 5, o = blockIdx.x & 31;
    int m = threadIdx.x;
    unsigned nk0 = g_keys[0], nk1 = g_keys[1];
    float thn = 0.0f, av = 0.0f;
    if (m < 34) {
        float th = theta_eff(theta1[m * 32 + o]);
        float u = tf_uniform(nk0, nk1, (unsigned)((n * 34 + m) * 32 + o));
        float noise = (u * 2.0f - 1.0f) * 0.05f + 1.0f;
        thn = th * noise;
        av = fabsf(thn);
    }
    sh[threadIdx.x] = av;
    __syncthreads();
    if (threadIdx.x == 0) {
        float s = 0.0f;
        for (int i = 0; i < 64; i++) s += sh[i];
        sh[0] = s + 1e-10f;
    }
    __syncthreads();
    float den = sh[0];
    if (m < 33) g_w1[(n * 33 + m) * 32 + o] = thn / den;
}

// ---------------- kernel 2: weights for pmac2 (reordered) ----------------
__global__ void k_prep_w2(const float* __restrict__ theta2) {
    __shared__ float sh[128];
    int n = blockIdx.x >> 5, o = blockIdx.x & 31;
    int tid = threadIdx.x;
    unsigned nk0 = g_keys[2], nk1 = g_keys[3];
    float part = 0.0f;
    for (int m = tid; m < 1058; m += 128) {
        float th = theta_eff(theta2[m * 32 + o]);
        float u = tf_uniform(nk0, nk1, (unsigned)((n * 1058 + m) * 32 + o));
        float noise = (u * 2.0f - 1.0f) * 0.05f + 1.0f;
        part += fabsf(th * noise);
    }
    sh[tid] = part;
    __syncthreads();
    for (int s = 64; s > 0; s >>= 1) {
        if (tid < s) sh[tid] += sh[tid + s];
        __syncthreads();
    }
    float den = sh[0] + 1e-10f;
    for (int m = tid; m < 1057; m += 128) {   // m=1057 (zeros row) excluded
        float th = theta_eff(theta2[m * 32 + o]);
        float u = tf_uniform(nk0, nk1, (unsigned)((n * 1058 + m) * 32 + o));
        float noise = (u * 2.0f - 1.0f) * 0.05f + 1.0f;
        float w = (th * noise) / den;
        int mm;
        if (m == 1056) mm = 1056;               // ones/bias row
        else {
            int c = m / 33, r = m % 33;
            mm = (r == 0) ? c : (32 + c * 32 + (r - 1));
        }
        g_w2[(n * 1057 + mm) * 32 + o] = w;
    }
}

// ---------------- kernel 3: pmac1 -> a1s[c][n][t][b] ----------------
// block = (n,b,t-half): 256 blocks x 128 threads
__global__ void __launch_bounds__(128) k_pmac1(const float* __restrict__ x) {
    __shared__ float w[33 * 32];
    int nb = blockIdx.x >> 1;
    int n = nb >> 5, b = nb & 31;
    int t = (blockIdx.x & 1) * 128 + threadIdx.x;
    for (int i = threadIdx.x; i < 33 * 32; i += 128) w[i] = g_w1[n * (33 * 32) + i];
    __syncthreads();
    float z[32];
#pragma unroll
    for (int o = 0; o < 32; o++) z[o] = w[32 * 32 + o];   // ones-row term
    const float* xp = x + ((n * 32 + b) * 32) * 256 + t;
#pragma unroll 4
    for (int m = 0; m < 32; m++) {
        float xv = xp[m * 256];
#pragma unroll
        for (int o = 0; o < 32; o++) z[o] = fmaf(xv, w[m * 32 + o], z[o]);
    }
#pragma unroll
    for (int o = 0; o < 32; o++) {
        float a = 0.05f + 0.5f * tanhf((z[o] - 0.3f) * 3.0f);
        g_a1s[((o * 4 + n) * 256 + t) * 32 + b] = a;
    }
}

// ---------------- kernel 4: beta tables, layout [n][t][k] ----------------
__global__ void __launch_bounds__(256) k_beta(const float* __restrict__ Rlf,
                                              const float* __restrict__ Clf) {
    int bank = blockIdx.y;
    int gid = blockIdx.x * 256 + threadIdx.x;     // 0 .. 1048575
    int k = gid & 1023;
    int n = (gid >> 10) & 3;
    int t = gid >> 12;
    int off = 4 + bank * 8;
    unsigned kR0 = g_keys[off + 0], kR1 = g_keys[off + 1];
    unsigned kC0 = g_keys[off + 2], kC1 = g_keys[off + 3];
    unsigned km0 = g_keys[off + 4], km1 = g_keys[off + 5];
    unsigned ctr = (unsigned)(((t * 1024) + k) * 4 + n);   // iota over (T,K,N,1)
    float nR = (tf_uniform(kR0, kR1, ctr) * 2.0f - 1.0f) * 0.05f + 1.0f;
    float nC = (tf_uniform(kC0, kC1, ctr) * 2.0f - 1.0f) * 0.05f + 1.0f;
    float mu = tf_uniform(km0, km1, ctr) * 0.2f + 1.0f;
    float R_ = Rlf[k * 2 + bank];
    float C_ = Clf[k * 2 + bank];
    float Rt = sigmoidf_(R_) * (1e7f - 1e5f) + 1e5f;
    float Ct = sigmoidf_(C_) * (1e-4f - 1e-7f) + 1e-7f;
    float RC = mu * (Rt * nR) * (Ct * nC);
    float beta = RC / (RC + 0.1f);
    float* dst = bank ? g_beta2 : g_beta1;
    dst[(n * 256 + t) * 1024 + k] = beta;
}

// ---------------- kernel 5: FUSED scan + pmac2 GEMM ----------------
// block = (n,b): 128 blocks x 1024 threads. Chunk = 8 timesteps.
// smem (floats): W[1057*32] | Y[1024][8] | RED[8][32][33] | A1[8][32]
#define SM_W   0
#define SM_Y   33824
#define SM_RED 42016
#define SM_A1  50464
#define SM_TOT 50720          // floats -> 202880 bytes

__global__ void __launch_bounds__(1024, 1) k_fused(float* __restrict__ out) {
    extern __shared__ float sm[];
    float* w_s   = sm + SM_W;
    float* y_s   = sm + SM_Y;
    float* red_s = sm + SM_RED;
    float* a1_s  = sm + SM_A1;

    int n = blockIdx.x >> 5, b = blockIdx.x & 31;
    int tid = threadIdx.x;

    // ---- preload full weight slice (1057x32 floats, 132 KiB) ----
    const float* wg = g_w2 + n * (1057 * 32);
    for (int i = tid; i < 1057 * 32; i += 1024) w_s[i] = wg[i];

    // ---- scan lane setup: thread = k ----
    int k = tid;
    int c = k >> 5;   // a1 channel; equals warp id
    unsigned sctr = (unsigned)((k * 4 + n) * 32 + b);
    float s1 = tf_uniform(g_keys[10], g_keys[11], sctr);
    float s2 = tf_uniform(g_keys[18], g_keys[19], sctr);
    const float* b1base = g_beta1 + n * 256 * 1024 + k;
    const float* b2base = g_beta2 + n * 256 * 1024 + k;
    const float* xbase  = g_a1s + ((c * 4 + n) * 256) * 32 + b;

    // ---- GEMM thread map: o-quad x t-pair x k-slice ----
    int o4 = (tid & 7) * 4;
    int t2 = (tid >> 3) & 3;
    int ks = tid >> 5;            // = warp id, k-slice of 32
    const float* wp = w_s + (32 + ks * 32) * 32;  // rows 32+k
    const float* yp = y_s + (ks * 32) * 8 + t2 * 2;

    // ---- reduce map ----
    int rt = tid >> 5, ro = tid & 31;   // valid for tid < 256

    __syncthreads();

    for (int ch = 0; ch < 32; ch++) {
        int t0 = ch * 8;

        // ===== scan 8 steps, buffer outputs in regs =====
        float yv[8];
#pragma unroll
        for (int tt = 0; tt < 8; tt++) {
            int t = t0 + tt;
            float b1 = b1base[t * 1024];
            float b2 = b2base[t * 1024];
            float xv = xbase[t * 32];
            if ((tid & 31) == 0) a1_s[tt * 32 + c] = xv;
            float y1 = s1;
            s1 = b1 * s1 + (1.0f - b1) * xv;
            yv[tt] = s2;                        // pre-update output
            s2 = b2 * s2 + (1.0f - b2) * y1;
        }
        *(float4*)(y_s + k * 8)     = make_float4(yv[0], yv[1], yv[2], yv[3]);
        *(float4*)(y_s + k * 8 + 4) = make_float4(yv[4], yv[5], yv[6], yv[7]);
        __syncthreads();

        // ===== GEMM over this chunk: acc[4o][2t] over 32 k =====
        float acc00 = 0.f, acc01 = 0.f, acc10 = 0.f, acc11 = 0.f;
        float acc20 = 0.f, acc21 = 0.f, acc30 = 0.f, acc31 = 0.f;
#pragma unroll 8
        for (int j = 0; j < 32; j++) {
            float4 w4 = *(const float4*)(wp + j * 32 + o4);
            float2 yy = *(const float2*)(yp + j * 8);
            acc00 = fmaf(w4.x, yy.x, acc00); acc01 = fmaf(w4.x, yy.y, acc01);
            acc10 = fmaf(w4.y, yy.x, acc10); acc11 = fmaf(w4.y, yy.y, acc11);
            acc20 = fmaf(w4.z, yy.x, acc20); acc21 = fmaf(w4.z, yy.y, acc21);
            acc30 = fmaf(w4.w, yy.x, acc30); acc31 = fmaf(w4.w, yy.y, acc31);
        }
        {
            int tA = t2 * 2, tB = t2 * 2 + 1;
            red_s[(tA * 32 + ks) * 33 + o4 + 0] = acc00;
            red_s[(tB * 32 + ks) * 33 + o4 + 0] = acc01;
            red_s[(tA * 32 + ks) * 33 + o4 + 1] = acc10;
            red_s[(tB * 32 + ks) * 33 + o4 + 1] = acc11;
            red_s[(tA * 32 + ks) * 33 + o4 + 2] = acc20;
            red_s[(tB * 32 + ks) * 33 + o4 + 2] = acc21;
            red_s[(tA * 32 + ks) * 33 + o4 + 3] = acc30;
            red_s[(tB * 32 + ks) * 33 + o4 + 3] = acc31;
        }
        __syncthreads();

        // ===== reduce + a1 term + bias + act + store =====
        if (tid < 256) {
            float z = w_s[1056 * 32 + ro];      // bias row
#pragma unroll 8
            for (int j = 0; j < 32; j++)
                z += red_s[(rt * 32 + j) * 33 + ro];
#pragma unroll 8
            for (int cc = 0; cc < 32; cc++)
                z = fmaf(w_s[cc * 32 + ro], a1_s[rt * 32 + cc], z);
            float a = 0.05f + 0.5f * tanhf((z - 0.3f) * 3.0f);
            out[((n * 32 + b) * 32 + ro) * 256 + t0 + rt] = a;
        }
        __syncthreads();
    }
}

// ---------------- launch ----------------
extern "C" void kernel_launch(void* const* d_in, const int* in_sizes, int n_in,
                              void* d_out, int out_size) {
    (void)in_sizes; (void)n_in; (void)out_size;
    const float* x      = (const float*)d_in[0];   // (4,32,32,256)
    const float* theta1 = (const float*)d_in[1];   // (34,32)
    const float* theta2 = (const float*)d_in[2];   // (1058,32)
    const float* Rlf    = (const float*)d_in[3];   // (32,32,2)
    const float* Clf    = (const float*)d_in[4];   // (32,32,2)
    float* out = (float*)d_out;

    static int smem_set = 0;
    if (!smem_set) {
        cudaFuncSetAttribute(k_fused, cudaFuncAttributeMaxDynamicSharedMemorySize,
                             SM_TOT * sizeof(float));
        smem_set = 1;
    }

    k_keys<<<1, 1>>>();
    k_prep_w1<<<128, 64>>>(theta1);
    k_prep_w2<<<128, 128>>>(theta2);
    k_pmac1<<<256, 128>>>(x);
    k_beta<<<dim3(4096, 2), 256>>>(Rlf, Clf);
    k_fused<<<128, 1024, SM_TOT * sizeof(float)>>>(out);
}

// round 4
// speedup vs baseline: 2.3245x; 1.0037x over previous
#include <cuda_runtime.h>
#include <stdint.h>

// ---------------- problem constants ----------------
#define NVAR 4
#define BATCH 32
#define TSTEPS 256
#define KLANES 1024          // NOUT * NFEAT

struct Keys { unsigned v[20]; };
// v[0..1]=k1(pmac1), v[2..3]=k4(pmac2), v[4+bank*8 ..]= {kR,kC,kmu,k0} pairs per bank

static __device__ float g_w2[NVAR * 1057 * 32];            // reordered: [0..31]=a1 ch, [32..1055]=y2 k, [1056]=bias
static __device__ float g_a1s[NVAR * BATCH * 32 * TSTEPS]; // [n][b][c][t]
static __device__ float g_beta1[NVAR * TSTEPS * KLANES];   // [n][t][k]
static __device__ float g_beta2[NVAR * TSTEPS * KLANES];

// ---------------- threefry2x32-20 (JAX-compatible), device ----------------
__device__ __forceinline__ void tf2x32(unsigned k0, unsigned k1,
                                       unsigned x0, unsigned x1,
                                       unsigned& o0, unsigned& o1) {
    unsigned ks2 = k0 ^ k1 ^ 0x1BD11BDAu;
    x0 += k0; x1 += k1;
#define TFR(r) { x0 += x1; x1 = (x1 << (r)) | (x1 >> (32 - (r))); x1 ^= x0; }
    TFR(13) TFR(15) TFR(26) TFR(6)
    x0 += k1; x1 += ks2 + 1u;
    TFR(17) TFR(29) TFR(16) TFR(24)
    x0 += ks2; x1 += k0 + 2u;
    TFR(13) TFR(15) TFR(26) TFR(6)
    x0 += k0; x1 += k1 + 3u;
    TFR(17) TFR(29) TFR(16) TFR(24)
    x0 += k1; x1 += ks2 + 4u;
    TFR(13) TFR(15) TFR(26) TFR(6)
    x0 += ks2; x1 += k0 + 5u;
#undef TFR
    o0 = x0; o1 = x1;
}

// partitionable-mode random_bits(32): counter = (hi=0, lo=i), bits = out0 ^ out1
__device__ __forceinline__ float tf_uniform(unsigned k0, unsigned k1, unsigned ctr) {
    unsigned o0, o1;
    tf2x32(k0, k1, 0u, ctr, o0, o1);
    unsigned bits = o0 ^ o1;
    return __uint_as_float((bits >> 9) | 0x3f800000u) - 1.0f;
}

__device__ __forceinline__ float sigmoidf_(float x) {
    return 1.0f / (1.0f + expf(-x));
}

__device__ __forceinline__ float theta_eff(float t) {
    t = fminf(fmaxf(t, -10.0f), 10.0f);
    if (fabsf(t) < 0.01f) t = 0.0f;
    return t;
}

// ================= megakernel A: beta | pmac1(+w1) | prep_w2 =================
// blocks [0..8191] beta, [8192..8319] pmac1, [8320..8447] prep_w2. 256 thr.
__global__ void __launch_bounds__(256) k_A(Keys kk,
                                           const float* __restrict__ x,
                                           const float* __restrict__ theta1,
                                           const float* __restrict__ theta2,
                                           const float* __restrict__ Rlf,
                                           const float* __restrict__ Clf) {
    int blk = blockIdx.x;
    int tid = threadIdx.x;

    if (blk < 8192) {
        // -------- beta tables, layout [n][t][k] --------
        unsigned gid = (unsigned)blk * 256u + (unsigned)tid;   // 0 .. 2M-1
        int bank = gid >> 20;
        unsigned rest = gid & 0xFFFFFu;
        int k = rest & 1023;
        int n = (rest >> 10) & 3;
        int t = rest >> 12;
        int off = 4 + bank * 8;
        unsigned ctr = (unsigned)(((t * 1024) + k) * 4 + n);   // iota over (T,K,N,1)
        float nR = (tf_uniform(kk.v[off + 0], kk.v[off + 1], ctr) * 2.0f - 1.0f) * 0.05f + 1.0f;
        float nC = (tf_uniform(kk.v[off + 2], kk.v[off + 3], ctr) * 2.0f - 1.0f) * 0.05f + 1.0f;
        float mu = tf_uniform(kk.v[off + 4], kk.v[off + 5], ctr) * 0.2f + 1.0f;
        float R_ = Rlf[k * 2 + bank];
        float C_ = Clf[k * 2 + bank];
        float Rt = sigmoidf_(R_) * (1e7f - 1e5f) + 1e5f;
        float Ct = sigmoidf_(C_) * (1e-4f - 1e-7f) + 1e-7f;
        float RC = mu * (Rt * nR) * (Ct * nC);
        float beta = RC / (RC + 0.1f);
        float* dst = bank ? g_beta2 : g_beta1;
        dst[(n * 256 + t) * 1024 + k] = beta;

    } else if (blk < 8320) {
        // -------- pmac1: block=(n,b), thread=t. inline w1 (per-n redundant). --------
        __shared__ float w[33 * 32];
        int blk2 = blk - 8192;
        int n = blk2 >> 5, b = blk2 & 31;
        if (tid < 32) {
            int o = tid;
            float den = 0.0f;
            for (int m = 0; m < 34; m++) {
                float th = theta_eff(theta1[m * 32 + o]);
                float u = tf_uniform(kk.v[0], kk.v[1], (unsigned)((n * 34 + m) * 32 + o));
                float noise = (u * 2.0f - 1.0f) * 0.05f + 1.0f;
                float thn = th * noise;
                den += fabsf(thn);
                if (m < 33) w[m * 32 + o] = thn;
            }
            den += 1e-10f;
            for (int m = 0; m < 33; m++) w[m * 32 + o] = w[m * 32 + o] / den;
        }
        __syncthreads();
        int t = tid;
        float z[32];
#pragma unroll
        for (int o = 0; o < 32; o++) z[o] = w[32 * 32 + o];   // ones-row term
        const float* xp = x + ((n * 32 + b) * 32) * 256 + t;
#pragma unroll 4
        for (int m = 0; m < 32; m++) {
            float xv = xp[m * 256];
#pragma unroll
            for (int o = 0; o < 32; o++) z[o] = fmaf(xv, w[m * 32 + o], z[o]);
        }
#pragma unroll
        for (int o = 0; o < 32; o++) {
            float a = 0.05f + 0.5f * tanhf((z[o] - 0.3f) * 3.0f);
            g_a1s[(((n * 32 + b) * 32) + o) * 256 + t] = a;   // t-coalesced
        }

    } else {
        // -------- prep_w2 (reordered): block=(n,o), 256 threads over m --------
        __shared__ float sh[256];
        int blk3 = blk - 8320;
        int n = blk3 >> 5, o = blk3 & 31;
        unsigned nk0 = kk.v[2], nk1 = kk.v[3];
        float part = 0.0f;
        for (int m = tid; m < 1058; m += 256) {
            float th = theta_eff(theta2[m * 32 + o]);
            float u = tf_uniform(nk0, nk1, (unsigned)((n * 1058 + m) * 32 + o));
            float noise = (u * 2.0f - 1.0f) * 0.05f + 1.0f;
            part += fabsf(th * noise);
        }
        sh[tid] = part;
        __syncthreads();
        for (int s = 128; s > 0; s >>= 1) {
            if (tid < s) sh[tid] += sh[tid + s];
            __syncthreads();
        }
        float den = sh[0] + 1e-10f;
        for (int m = tid; m < 1057; m += 256) {   // m=1057 (zeros row) excluded
            float th = theta_eff(theta2[m * 32 + o]);
            float u = tf_uniform(nk0, nk1, (unsigned)((n * 1058 + m) * 32 + o));
            float noise = (u * 2.0f - 1.0f) * 0.05f + 1.0f;
            float wv = (th * noise) / den;
            int mm;
            if (m == 1056) mm = 1056;               // ones/bias row
            else {
                int c = m / 33, r = m % 33;
                mm = (r == 0) ? c : (32 + c * 32 + (r - 1));
            }
            g_w2[(n * 1057 + mm) * 32 + o] = wv;
        }
    }
}

// ================= FUSED scan + pmac2 GEMM =================
// block = (n,b): 128 blocks x 1024 threads. Chunk = 8 timesteps.
// smem (floats): W[1057*32] | Y[1024][8] | RED[8][32][33] | A1[8][32]
#define SM_W   0
#define SM_Y   33824
#define SM_RED 42016
#define SM_A1  50464
#define SM_TOT 50720          // floats -> 202880 bytes

__global__ void __launch_bounds__(1024, 1) k_fused(Keys kk, float* __restrict__ out) {
    extern __shared__ float sm[];
    float* w_s   = sm + SM_W;
    float* y_s   = sm + SM_Y;
    float* red_s = sm + SM_RED;
    float* a1_s  = sm + SM_A1;

    int n = blockIdx.x >> 5, b = blockIdx.x & 31;
    int tid = threadIdx.x;

    // ---- preload full weight slice (1057x32 floats, 132 KiB) ----
    const float* wg = g_w2 + n * (1057 * 32);
    for (int i = tid; i < 1057 * 32; i += 1024) w_s[i] = wg[i];

    // ---- scan lane setup: thread = k ----
    int k = tid;
    int c = k >> 5;   // a1 channel; equals warp id
    unsigned sctr = (unsigned)((k * 4 + n) * 32 + b);
    float s1 = tf_uniform(kk.v[10], kk.v[11], sctr);
    float s2 = tf_uniform(kk.v[18], kk.v[19], sctr);
    const float* b1base = g_beta1 + n * 256 * 1024 + k;
    const float* b2base = g_beta2 + n * 256 * 1024 + k;
    const float* xbase  = g_a1s + (((n * 32 + b) * 32) + c) * 256;  // [n][b][c][t]

    // ---- GEMM thread map: o-quad x t-pair x k-slice ----
    int o4 = (tid & 7) * 4;
    int t2 = (tid >> 3) & 3;
    int ks = tid >> 5;            // = warp id, k-slice of 32
    const float* wp = w_s + (32 + ks * 32) * 32;  // rows 32+k
    const float* yp = y_s + (ks * 32) * 8 + t2 * 2;

    // ---- reduce map ----
    int rt = tid >> 5, ro = tid & 31;   // valid for tid < 256

    __syncthreads();

    for (int ch = 0; ch < 32; ch++) {
        int t0 = ch * 8;

        // ===== scan 8 steps, buffer outputs in regs =====
        float yv[8];
#pragma unroll
        for (int tt = 0; tt < 8; tt++) {
            int t = t0 + tt;
            float b1 = b1base[t * 1024];
            float b2 = b2base[t * 1024];
            float xv = xbase[t];
            if ((tid & 31) == 0) a1_s[tt * 32 + c] = xv;
            float y1 = s1;
            s1 = b1 * s1 + (1.0f - b1) * xv;
            yv[tt] = s2;                        // pre-update output
            s2 = b2 * s2 + (1.0f - b2) * y1;
        }
        *(float4*)(y_s + k * 8)     = make_float4(yv[0], yv[1], yv[2], yv[3]);
        *(float4*)(y_s + k * 8 + 4) = make_float4(yv[4], yv[5], yv[6], yv[7]);
        __syncthreads();

        // ===== GEMM over this chunk: acc[4o][2t] over 32 k =====
        float acc00 = 0.f, acc01 = 0.f, acc10 = 0.f, acc11 = 0.f;
        float acc20 = 0.f, acc21 = 0.f, acc30 = 0.f, acc31 = 0.f;
#pragma unroll 8
        for (int j = 0; j < 32; j++) {
            float4 w4 = *(const float4*)(wp + j * 32 + o4);
            float2 yy = *(const float2*)(yp + j * 8);
            acc00 = fmaf(w4.x, yy.x, acc00); acc01 = fmaf(w4.x, yy.y, acc01);
            acc10 = fmaf(w4.y, yy.x, acc10); acc11 = fmaf(w4.y, yy.y, acc11);
            acc20 = fmaf(w4.z, yy.x, acc20); acc21 = fmaf(w4.z, yy.y, acc21);
            acc30 = fmaf(w4.w, yy.x, acc30); acc31 = fmaf(w4.w, yy.y, acc31);
        }
        {
            int tA = t2 * 2, tB = t2 * 2 + 1;
            red_s[(tA * 32 + ks) * 33 + o4 + 0] = acc00;
            red_s[(tB * 32 + ks) * 33 + o4 + 0] = acc01;
            red_s[(tA * 32 + ks) * 33 + o4 + 1] = acc10;
            red_s[(tB * 32 + ks) * 33 + o4 + 1] = acc11;
            red_s[(tA * 32 + ks) * 33 + o4 + 2] = acc20;
            red_s[(tB * 32 + ks) * 33 + o4 + 2] = acc21;
            red_s[(tA * 32 + ks) * 33 + o4 + 3] = acc30;
            red_s[(tB * 32 + ks) * 33 + o4 + 3] = acc31;
        }
        __syncthreads();

        // ===== reduce + a1 term + bias + act + store =====
        if (tid < 256) {
            float z = w_s[1056 * 32 + ro];      // bias row
#pragma unroll 8
            for (int j = 0; j < 32; j++)
                z += red_s[(rt * 32 + j) * 33 + ro];
#pragma unroll 8
            for (int cc = 0; cc < 32; cc++)
                z = fmaf(w_s[cc * 32 + ro], a1_s[rt * 32 + cc], z);
            float a = 0.05f + 0.5f * tanhf((z - 0.3f) * 3.0f);
            out[((n * 32 + b) * 32 + ro) * 256 + t0 + rt] = a;
        }
        __syncthreads();
    }
}

// ---------------- host-side threefry for key derivation ----------------
static void h_tf2x32(unsigned k0, unsigned k1, unsigned x0, unsigned x1,
                     unsigned& o0, unsigned& o1) {
    unsigned ks2 = k0 ^ k1 ^ 0x1BD11BDAu;
    x0 += k0; x1 += k1;
#define HTFR(r) { x0 += x1; x1 = (x1 << (r)) | (x1 >> (32 - (r))); x1 ^= x0; }
    HTFR(13) HTFR(15) HTFR(26) HTFR(6)
    x0 += k1; x1 += ks2 + 1u;
    HTFR(17) HTFR(29) HTFR(16) HTFR(24)
    x0 += ks2; x1 += k0 + 2u;
    HTFR(13) HTFR(15) HTFR(26) HTFR(6)
    x0 += k0; x1 += k1 + 3u;
    HTFR(17) HTFR(29) HTFR(16) HTFR(24)
    x0 += k1; x1 += ks2 + 4u;
    HTFR(13) HTFR(15) HTFR(26) HTFR(6)
    x0 += ks2; x1 += k0 + 5u;
#undef HTFR
    o0 = x0; o1 = x1;
}

// ---------------- launch ----------------
extern "C" void kernel_launch(void* const* d_in, const int* in_sizes, int n_in,
                              void* d_out, int out_size) {
    (void)in_sizes; (void)n_in; (void)out_size;
    const float* x      = (const float*)d_in[0];   // (4,32,32,256)
    const float* theta1 = (const float*)d_in[1];   // (34,32)
    const float* theta2 = (const float*)d_in[2];   // (1058,32)
    const float* Rlf    = (const float*)d_in[3];   // (32,32,2)
    const float* Clf    = (const float*)d_in[4];   // (32,32,2)
    float* out = (float*)d_out;

    // keys: root = key(42); children 0..3 = threefry(root,(0,i)); banks split further
    Keys kk;
    unsigned ck[8];
    for (int i = 0; i < 4; i++) h_tf2x32(0u, 42u, 0u, (unsigned)i, ck[2 * i], ck[2 * i + 1]);
    kk.v[0] = ck[0]; kk.v[1] = ck[1];   // k1 (pmac1 noise)
    kk.v[2] = ck[6]; kk.v[3] = ck[7];   // k4 (pmac2 noise)
    for (int bank = 0; bank < 2; bank++) {
        unsigned b0 = ck[2 + 2 * bank], b1 = ck[3 + 2 * bank];  // k2 / k3
        for (int j = 0; j < 4; j++)
            h_tf2x32(b0, b1, 0u, (unsigned)j,
                     kk.v[4 + bank * 8 + 2 * j], kk.v[4 + bank * 8 + 2 * j + 1]);
    }

    static int smem_set = 0;
    if (!smem_set) {
        cudaFuncSetAttribute(k_fused, cudaFuncAttributeMaxDynamicSharedMemorySize,
                             SM_TOT * sizeof(float));
        smem_set = 1;
    }

    k_A<<<8448, 256>>>(kk, x, theta1, theta2, Rlf, Clf);
    k_fused<<<128, 1024, SM_TOT * sizeof(float)>>>(kk, out);
}

// round 5
// speedup vs baseline: 2.5574x; 1.1002x over previous
#include <cuda_runtime.h>
#include <stdint.h>

// ---------------- problem constants ----------------
#define NVAR 4
#define BATCH 32
#define TSTEPS 256
#define KLANES 1024          // NOUT * NFEAT

struct Keys { unsigned v[20]; };
// v[0..1]=k1(pmac1), v[2..3]=k4(pmac2), v[4+bank*8 ..]= {kR,kC,kmu,k0} pairs per bank

static __device__ float g_w2[NVAR * 1057 * 32];            // reordered: [0..31]=a1 ch, [32..1055]=y2 k, [1056]=bias
static __device__ float g_a1s[NVAR * BATCH * 32 * TSTEPS]; // [n][b][c][t]
static __device__ float g_beta1[NVAR * TSTEPS * KLANES];   // [n][t][k]
static __device__ float g_beta2[NVAR * TSTEPS * KLANES];

// ---------------- threefry2x32-20 (JAX-compatible), device ----------------
__device__ __forceinline__ void tf2x32(unsigned k0, unsigned k1,
                                       unsigned x0, unsigned x1,
                                       unsigned& o0, unsigned& o1) {
    unsigned ks2 = k0 ^ k1 ^ 0x1BD11BDAu;
    x0 += k0; x1 += k1;
#define TFR(r) { x0 += x1; x1 = (x1 << (r)) | (x1 >> (32 - (r))); x1 ^= x0; }
    TFR(13) TFR(15) TFR(26) TFR(6)
    x0 += k1; x1 += ks2 + 1u;
    TFR(17) TFR(29) TFR(16) TFR(24)
    x0 += ks2; x1 += k0 + 2u;
    TFR(13) TFR(15) TFR(26) TFR(6)
    x0 += k0; x1 += k1 + 3u;
    TFR(17) TFR(29) TFR(16) TFR(24)
    x0 += k1; x1 += ks2 + 4u;
    TFR(13) TFR(15) TFR(26) TFR(6)
    x0 += ks2; x1 += k0 + 5u;
#undef TFR
    o0 = x0; o1 = x1;
}

// partitionable-mode random_bits(32): counter = (hi=0, lo=i), bits = out0 ^ out1
__device__ __forceinline__ float tf_uniform(unsigned k0, unsigned k1, unsigned ctr) {
    unsigned o0, o1;
    tf2x32(k0, k1, 0u, ctr, o0, o1);
    unsigned bits = o0 ^ o1;
    return __uint_as_float((bits >> 9) | 0x3f800000u) - 1.0f;
}

__device__ __forceinline__ float sigmoidf_(float x) {
    return 1.0f / (1.0f + expf(-x));
}

__device__ __forceinline__ float theta_eff(float t) {
    t = fminf(fmaxf(t, -10.0f), 10.0f);
    if (fabsf(t) < 0.01f) t = 0.0f;
    return t;
}

// ================= megakernel A: beta | pmac1(+w1) | prep_w2 =================
// blocks [0..8191] beta, [8192..8319] pmac1, [8320..8447] prep_w2. 256 thr.
__global__ void __launch_bounds__(256) k_A(Keys kk,
                                           const float* __restrict__ x,
                                           const float* __restrict__ theta1,
                                           const float* __restrict__ theta2,
                                           const float* __restrict__ Rlf,
                                           const float* __restrict__ Clf) {
    int blk = blockIdx.x;
    int tid = threadIdx.x;

    if (blk < 8192) {
        // -------- beta tables, layout [n][t][k] --------
        unsigned gid = (unsigned)blk * 256u + (unsigned)tid;   // 0 .. 2M-1
        int bank = gid >> 20;
        unsigned rest = gid & 0xFFFFFu;
        int k = rest & 1023;
        int n = (rest >> 10) & 3;
        int t = rest >> 12;
        int off = 4 + bank * 8;
        unsigned ctr = (unsigned)(((t * 1024) + k) * 4 + n);   // iota over (T,K,N,1)
        float nR = (tf_uniform(kk.v[off + 0], kk.v[off + 1], ctr) * 2.0f - 1.0f) * 0.05f + 1.0f;
        float nC = (tf_uniform(kk.v[off + 2], kk.v[off + 3], ctr) * 2.0f - 1.0f) * 0.05f + 1.0f;
        float mu = tf_uniform(kk.v[off + 4], kk.v[off + 5], ctr) * 0.2f + 1.0f;
        float R_ = Rlf[k * 2 + bank];
        float C_ = Clf[k * 2 + bank];
        float Rt = sigmoidf_(R_) * (1e7f - 1e5f) + 1e5f;
        float Ct = sigmoidf_(C_) * (1e-4f - 1e-7f) + 1e-7f;
        float RC = mu * (Rt * nR) * (Ct * nC);
        float beta = RC / (RC + 0.1f);
        float* dst = bank ? g_beta2 : g_beta1;
        dst[(n * 256 + t) * 1024 + k] = beta;

    } else if (blk < 8320) {
        // -------- pmac1: block=(n,b), thread=t. inline w1 (per-n redundant). --------
        __shared__ float w[33 * 32];
        int blk2 = blk - 8192;
        int n = blk2 >> 5, b = blk2 & 31;
        if (tid < 32) {
            int o = tid;
            float den = 0.0f;
            for (int m = 0; m < 34; m++) {
                float th = theta_eff(theta1[m * 32 + o]);
                float u = tf_uniform(kk.v[0], kk.v[1], (unsigned)((n * 34 + m) * 32 + o));
                float noise = (u * 2.0f - 1.0f) * 0.05f + 1.0f;
                float thn = th * noise;
                den += fabsf(thn);
                if (m < 33) w[m * 32 + o] = thn;
            }
            den += 1e-10f;
            for (int m = 0; m < 33; m++) w[m * 32 + o] = w[m * 32 + o] / den;
        }
        __syncthreads();
        int t = tid;
        float z[32];
#pragma unroll
        for (int o = 0; o < 32; o++) z[o] = w[32 * 32 + o];   // ones-row term
        const float* xp = x + ((n * 32 + b) * 32) * 256 + t;
#pragma unroll 4
        for (int m = 0; m < 32; m++) {
            float xv = xp[m * 256];
#pragma unroll
            for (int o = 0; o < 32; o++) z[o] = fmaf(xv, w[m * 32 + o], z[o]);
        }
#pragma unroll
        for (int o = 0; o < 32; o++) {
            float a = 0.05f + 0.5f * tanhf((z[o] - 0.3f) * 3.0f);
            g_a1s[(((n * 32 + b) * 32) + o) * 256 + t] = a;   // t-coalesced
        }

    } else {
        // -------- prep_w2 (reordered): block=(n,o), 256 threads over m --------
        __shared__ float sh[256];
        int blk3 = blk - 8320;
        int n = blk3 >> 5, o = blk3 & 31;
        unsigned nk0 = kk.v[2], nk1 = kk.v[3];
        float part = 0.0f;
        for (int m = tid; m < 1058; m += 256) {
            float th = theta_eff(theta2[m * 32 + o]);
            float u = tf_uniform(nk0, nk1, (unsigned)((n * 1058 + m) * 32 + o));
            float noise = (u * 2.0f - 1.0f) * 0.05f + 1.0f;
            part += fabsf(th * noise);
        }
        sh[tid] = part;
        __syncthreads();
        for (int s = 128; s > 0; s >>= 1) {
            if (tid < s) sh[tid] += sh[tid + s];
            __syncthreads();
        }
        float den = sh[0] + 1e-10f;
        for (int m = tid; m < 1057; m += 256) {   // m=1057 (zeros row) excluded
            float th = theta_eff(theta2[m * 32 + o]);
            float u = tf_uniform(nk0, nk1, (unsigned)((n * 1058 + m) * 32 + o));
            float noise = (u * 2.0f - 1.0f) * 0.05f + 1.0f;
            float wv = (th * noise) / den;
            int mm;
            if (m == 1056) mm = 1056;               // ones/bias row
            else {
                int c = m / 33, r = m % 33;
                mm = (r == 0) ? c : (32 + c * 32 + (r - 1));
            }
            g_w2[(n * 1057 + mm) * 32 + o] = wv;
        }
    }
}

// ================= FUSED scan + pmac2 GEMM (register-resident W) =================
// block = (n,b): 128 blocks x 1024 threads. Chunk = 8 timesteps.
// Warp = k-slice of 32 (ks). Lane = o. Each lane holds W[k=ks*32+j][o=lane], j=0..31
// in registers, accumulates all 8 t for its o over its k-slice.
// smem (floats): Wsmall[33*32] | Y[1024][8] | RED[8][32][33] | A1[8][32]
#define SM_WS  0
#define SM_Y   1056
#define SM_RED 9248
#define SM_A1  17696
#define SM_TOT 17952          // floats -> 71808 bytes

__global__ void __launch_bounds__(1024, 1) k_fused(Keys kk, float* __restrict__ out) {
    extern __shared__ float sm[];
    float* ws_s  = sm + SM_WS;    // rows 0..31 = a1-channel weights, row 32 = bias
    float* y_s   = sm + SM_Y;
    float* red_s = sm + SM_RED;
    float* a1_s  = sm + SM_A1;

    int n = blockIdx.x >> 5, b = blockIdx.x & 31;
    int tid  = threadIdx.x;
    int ks   = tid >> 5;          // warp id = k-slice
    int lane = tid & 31;          // = o in GEMM phase

    const float* wg = g_w2 + n * (1057 * 32);

    // ---- small weight block to smem: a1 rows + bias ----
    if (tid < 1024) ws_s[tid] = wg[tid];                    // rows 0..31
    if (tid < 32)   ws_s[1024 + tid] = wg[1056 * 32 + tid]; // bias row

    // ---- register-resident W slice: W[32+ks*32+j][lane], j=0..31 ----
    float wreg[32];
    {
        const float* wp = wg + (32 + ks * 32) * 32 + lane;
#pragma unroll
        for (int j = 0; j < 32; j++) wreg[j] = wp[j * 32];  // coalesced (lane fastest)
    }

    // ---- scan lane setup: thread = k = tid ----
    int k = tid;
    int c = ks;                   // a1 channel = warp id
    unsigned sctr = (unsigned)((k * 4 + n) * 32 + b);
    float s1 = tf_uniform(kk.v[10], kk.v[11], sctr);
    float s2 = tf_uniform(kk.v[18], kk.v[19], sctr);
    const float* b1base = g_beta1 + n * 256 * 1024 + k;
    const float* b2base = g_beta2 + n * 256 * 1024 + k;
    const float* xbase  = g_a1s + (((n * 32 + b) * 32) + c) * 256;  // [n][b][c][t]

    // ---- reduce map (tid < 256) ----
    int rt = tid >> 5, ro = tid & 31;

    __syncthreads();

    for (int ch = 0; ch < 32; ch++) {
        int t0 = ch * 8;

        // ===== scan 8 steps, buffer outputs in regs =====
        float yv[8];
#pragma unroll
        for (int tt = 0; tt < 8; tt++) {
            int t = t0 + tt;
            float b1 = b1base[t * 1024];
            float b2 = b2base[t * 1024];
            float xv = xbase[t];
            if (lane == 0) a1_s[tt * 32 + c] = xv;
            float y1 = s1;
            s1 = b1 * s1 + (1.0f - b1) * xv;
            yv[tt] = s2;                        // pre-update output
            s2 = b2 * s2 + (1.0f - b2) * y1;
        }
        *(float4*)(y_s + k * 8)     = make_float4(yv[0], yv[1], yv[2], yv[3]);
        *(float4*)(y_s + k * 8 + 4) = make_float4(yv[4], yv[5], yv[6], yv[7]);
        __syncthreads();

        // ===== GEMM: lane=o accumulates 8 t over its 32-k slice =====
        float a0 = 0.f, a1v = 0.f, a2 = 0.f, a3 = 0.f;
        float a4 = 0.f, a5 = 0.f, a6 = 0.f, a7 = 0.f;
        const float* yrow = y_s + ks * 256;     // 32 rows of 8
#pragma unroll
        for (int j = 0; j < 32; j++) {
            float4 ya = *(const float4*)(yrow + j * 8);      // broadcast
            float4 yb = *(const float4*)(yrow + j * 8 + 4);  // broadcast
            float w = wreg[j];
            a0 = fmaf(w, ya.x, a0); a1v = fmaf(w, ya.y, a1v);
            a2 = fmaf(w, ya.z, a2); a3 = fmaf(w, ya.w, a3);
            a4 = fmaf(w, yb.x, a4); a5 = fmaf(w, yb.y, a5);
            a6 = fmaf(w, yb.z, a6); a7 = fmaf(w, yb.w, a7);
        }
        red_s[(0 * 32 + ks) * 33 + lane] = a0;
        red_s[(1 * 32 + ks) * 33 + lane] = a1v;
        red_s[(2 * 32 + ks) * 33 + lane] = a2;
        red_s[(3 * 32 + ks) * 33 + lane] = a3;
        red_s[(4 * 32 + ks) * 33 + lane] = a4;
        red_s[(5 * 32 + ks) * 33 + lane] = a5;
        red_s[(6 * 32 + ks) * 33 + lane] = a6;
        red_s[(7 * 32 + ks) * 33 + lane] = a7;
        __syncthreads();

        // ===== reduce + a1 term + bias + act + store =====
        if (tid < 256) {
            float z = ws_s[1024 + ro];          // bias
#pragma unroll 8
            for (int j = 0; j < 32; j++)
                z += red_s[(rt * 32 + j) * 33 + ro];
#pragma unroll 8
            for (int cc = 0; cc < 32; cc++)
                z = fmaf(ws_s[cc * 32 + ro], a1_s[rt * 32 + cc], z);
            float a = 0.05f + 0.5f * tanhf((z - 0.3f) * 3.0f);
            out[((n * 32 + b) * 32 + ro) * 256 + t0 + rt] = a;
        }
        __syncthreads();
    }
}

// ---------------- host-side threefry for key derivation ----------------
static void h_tf2x32(unsigned k0, unsigned k1, unsigned x0, unsigned x1,
                     unsigned& o0, unsigned& o1) {
    unsigned ks2 = k0 ^ k1 ^ 0x1BD11BDAu;
    x0 += k0; x1 += k1;
#define HTFR(r) { x0 += x1; x1 = (x1 << (r)) | (x1 >> (32 - (r))); x1 ^= x0; }
    HTFR(13) HTFR(15) HTFR(26) HTFR(6)
    x0 += k1; x1 += ks2 + 1u;
    HTFR(17) HTFR(29) HTFR(16) HTFR(24)
    x0 += ks2; x1 += k0 + 2u;
    HTFR(13) HTFR(15) HTFR(26) HTFR(6)
    x0 += k0; x1 += k1 + 3u;
    HTFR(17) HTFR(29) HTFR(16) HTFR(24)
    x0 += k1; x1 += ks2 + 4u;
    HTFR(13) HTFR(15) HTFR(26) HTFR(6)
    x0 += ks2; x1 += k0 + 5u;
#undef HTFR
    o0 = x0; o1 = x1;
}

// ---------------- launch ----------------
extern "C" void kernel_launch(void* const* d_in, const int* in_sizes, int n_in,
                              void* d_out, int out_size) {
    (void)in_sizes; (void)n_in; (void)out_size;
    const float* x      = (const float*)d_in[0];   // (4,32,32,256)
    const float* theta1 = (const float*)d_in[1];   // (34,32)
    const float* theta2 = (const float*)d_in[2];   // (1058,32)
    const float* Rlf    = (const float*)d_in[3];   // (32,32,2)
    const float* Clf    = (const float*)d_in[4];   // (32,32,2)
    float* out = (float*)d_out;

    // keys: root = key(42); children 0..3 = threefry(root,(0,i)); banks split further
    Keys kk;
    unsigned ck[8];
    for (int i = 0; i < 4; i++) h_tf2x32(0u, 42u, 0u, (unsigned)i, ck[2 * i], ck[2 * i + 1]);
    kk.v[0] = ck[0]; kk.v[1] = ck[1];   // k1 (pmac1 noise)
    kk.v[2] = ck[6]; kk.v[3] = ck[7];   // k4 (pmac2 noise)
    for (int bank = 0; bank < 2; bank++) {
        unsigned b0 = ck[2 + 2 * bank], b1 = ck[3 + 2 * bank];  // k2 / k3
        for (int j = 0; j < 4; j++)
            h_tf2x32(b0, b1, 0u, (unsigned)j,
                     kk.v[4 + bank * 8 + 2 * j], kk.v[4 + bank * 8 + 2 * j + 1]);
    }

    static int smem_set = 0;
    if (!smem_set) {
        cudaFuncSetAttribute(k_fused, cudaFuncAttributeMaxDynamicSharedMemorySize,
                             SM_TOT * sizeof(float));
        smem_set = 1;
    }

    k_A<<<8448, 256>>>(kk, x, theta1, theta2, Rlf, Clf);
    k_fused<<<128, 1024, SM_TOT * sizeof(float)>>>(kk, out);
}

// round 7
// speedup vs baseline: 2.7889x; 1.0905x over previous
#include <cuda_runtime.h>
#include <stdint.h>

// ---------------- problem constants ----------------
#define NVAR 4
#define BATCH 32
#define TSTEPS 256
#define KLANES 1024          // NOUT * NFEAT

struct Keys { unsigned v[20]; };

static __device__ float g_w2[NVAR * 1057 * 32];            // reordered: [0..31]=a1 ch, [32..1055]=y2 k, [1056]=bias
static __device__ float g_a1s[NVAR * BATCH * 32 * TSTEPS]; // [n][b][c][t]
static __device__ float g_beta1[NVAR * TSTEPS * KLANES];   // [n][t][k]
static __device__ float g_beta2[NVAR * TSTEPS * KLANES];

// ---------------- threefry2x32-20 (JAX-compatible), device ----------------
__device__ __forceinline__ void tf2x32(unsigned k0, unsigned k1,
                                       unsigned x0, unsigned x1,
                                       unsigned& o0, unsigned& o1) {
    unsigned ks2 = k0 ^ k1 ^ 0x1BD11BDAu;
    x0 += k0; x1 += k1;
#define TFR(r) { x0 += x1; x1 = (x1 << (r)) | (x1 >> (32 - (r))); x1 ^= x0; }
    TFR(13) TFR(15) TFR(26) TFR(6)
    x0 += k1; x1 += ks2 + 1u;
    TFR(17) TFR(29) TFR(16) TFR(24)
    x0 += ks2; x1 += k0 + 2u;
    TFR(13) TFR(15) TFR(26) TFR(6)
    x0 += k0; x1 += k1 + 3u;
    TFR(17) TFR(29) TFR(16) TFR(24)
    x0 += k1; x1 += ks2 + 4u;
    TFR(13) TFR(15) TFR(26) TFR(6)
    x0 += ks2; x1 += k0 + 5u;
#undef TFR
    o0 = x0; o1 = x1;
}

__device__ __forceinline__ float tf_uniform(unsigned k0, unsigned k1, unsigned ctr) {
    unsigned o0, o1;
    tf2x32(k0, k1, 0u, ctr, o0, o1);
    unsigned bits = o0 ^ o1;
    return __uint_as_float((bits >> 9) | 0x3f800000u) - 1.0f;
}

__device__ __forceinline__ float sigmoidf_(float x) {
    return 1.0f / (1.0f + expf(-x));
}

__device__ __forceinline__ float theta_eff(float t) {
    t = fminf(fmaxf(t, -10.0f), 10.0f);
    if (fabsf(t) < 0.01f) t = 0.0f;
    return t;
}

// ---------------- cp.async helpers ----------------
__device__ __forceinline__ void cp16(uint32_t smem_addr, const void* gptr) {
    asm volatile("cp.async.ca.shared.global [%0], [%1], 16;\n"
                 :: "r"(smem_addr), "l"(gptr));
}
__device__ __forceinline__ void cp_commit() {
    asm volatile("cp.async.commit_group;\n" ::: "memory");
}
__device__ __forceinline__ void cp_wait0() {
    asm volatile("cp.async.wait_group 0;\n" ::: "memory");
}

// ================= megakernel A: beta | pmac1(+w1) | prep_w2 =================
__global__ void __launch_bounds__(256) k_A(Keys kk,
                                           const float* __restrict__ x,
                                           const float* __restrict__ theta1,
                                           const float* __restrict__ theta2,
                                           const float* __restrict__ Rlf,
                                           const float* __restrict__ Clf) {
    int blk = blockIdx.x;
    int tid = threadIdx.x;

    if (blk < 8192) {
        // -------- beta tables, layout [n][t][k] --------
        unsigned gid = (unsigned)blk * 256u + (unsigned)tid;   // 0 .. 2M-1
        int bank = gid >> 20;
        unsigned rest = gid & 0xFFFFFu;
        int k = rest & 1023;
        int n = (rest >> 10) & 3;
        int t = rest >> 12;
        int off = 4 + bank * 8;
        unsigned ctr = (unsigned)(((t * 1024) + k) * 4 + n);   // iota over (T,K,N,1)
        float nR = (tf_uniform(kk.v[off + 0], kk.v[off + 1], ctr) * 2.0f - 1.0f) * 0.05f + 1.0f;
        float nC = (tf_uniform(kk.v[off + 2], kk.v[off + 3], ctr) * 2.0f - 1.0f) * 0.05f + 1.0f;
        float mu = tf_uniform(kk.v[off + 4], kk.v[off + 5], ctr) * 0.2f + 1.0f;
        float R_ = Rlf[k * 2 + bank];
        float C_ = Clf[k * 2 + bank];
        float Rt = sigmoidf_(R_) * (1e7f - 1e5f) + 1e5f;
        float Ct = sigmoidf_(C_) * (1e-4f - 1e-7f) + 1e-7f;
        float RC = mu * (Rt * nR) * (Ct * nC);
        float beta = RC / (RC + 0.1f);
        float* dst = bank ? g_beta2 : g_beta1;
        dst[(n * 256 + t) * 1024 + k] = beta;

    } else if (blk < 8320) {
        // -------- pmac1: block=(n,b), thread=t --------
        __shared__ float w[33 * 32];
        int blk2 = blk - 8192;
        int n = blk2 >> 5, b = blk2 & 31;
        if (tid < 32) {
            int o = tid;
            float den = 0.0f;
            for (int m = 0; m < 34; m++) {
                float th = theta_eff(theta1[m * 32 + o]);
                float u = tf_uniform(kk.v[0], kk.v[1], (unsigned)((n * 34 + m) * 32 + o));
                float noise = (u * 2.0f - 1.0f) * 0.05f + 1.0f;
                float thn = th * noise;
                den += fabsf(thn);
                if (m < 33) w[m * 32 + o] = thn;
            }
            den += 1e-10f;
            for (int m = 0; m < 33; m++) w[m * 32 + o] = w[m * 32 + o] / den;
        }
        __syncthreads();
        int t = tid;
        float z[32];
#pragma unroll
        for (int o = 0; o < 32; o++) z[o] = w[32 * 32 + o];
        const float* xp = x + ((n * 32 + b) * 32) * 256 + t;
#pragma unroll 4
        for (int m = 0; m < 32; m++) {
            float xv = xp[m * 256];
#pragma unroll
            for (int o = 0; o < 32; o++) z[o] = fmaf(xv, w[m * 32 + o], z[o]);
        }
#pragma unroll
        for (int o = 0; o < 32; o++) {
            float a = 0.05f + 0.5f * tanhf((z[o] - 0.3f) * 3.0f);
            g_a1s[(((n * 32 + b) * 32) + o) * 256 + t] = a;
        }

    } else {
        // -------- prep_w2 (reordered) --------
        __shared__ float sh[256];
        int blk3 = blk - 8320;
        int n = blk3 >> 5, o = blk3 & 31;
        unsigned nk0 = kk.v[2], nk1 = kk.v[3];
        float part = 0.0f;
        for (int m = tid; m < 1058; m += 256) {
            float th = theta_eff(theta2[m * 32 + o]);
            float u = tf_uniform(nk0, nk1, (unsigned)((n * 1058 + m) * 32 + o));
            float noise = (u * 2.0f - 1.0f) * 0.05f + 1.0f;
            part += fabsf(th * noise);
        }
        sh[tid] = part;
        __syncthreads();
        for (int s = 128; s > 0; s >>= 1) {
            if (tid < s) sh[tid] += sh[tid + s];
            __syncthreads();
        }
        float den = sh[0] + 1e-10f;
        for (int m = tid; m < 1057; m += 256) {
            float th = theta_eff(theta2[m * 32 + o]);
            float u = tf_uniform(nk0, nk1, (unsigned)((n * 1058 + m) * 32 + o));
            float noise = (u * 2.0f - 1.0f) * 0.05f + 1.0f;
            float wv = (th * noise) / den;
            int mm;
            if (m == 1056) mm = 1056;
            else {
                int c = m / 33, r = m % 33;
                mm = (r == 0) ? c : (32 + c * 32 + (r - 1));
            }
            g_w2[(n * 1057 + mm) * 32 + o] = wv;
        }
    }
}

// ================= FUSED scan + pmac2 GEMM (FFMA2 + cp.async betas) =================
// block = (n,b): 128 blocks x 1024 threads. Chunk = 8 timesteps.
// smem (floats): WS[33*32] | Y[1024][12] | RED[8][32][33] | A1[8][32] | BB[2][2][8][1024]
#define SM_WS  0
#define SM_Y   1056
#define SM_RED 13344
#define SM_A1  21792
#define SM_BB  22048
#define SM_TOT 54816          // floats -> 219264 bytes

__global__ void __launch_bounds__(1024, 1) k_fused(Keys kk, float* __restrict__ out) {
    extern __shared__ float sm[];
    float* ws_s  = sm + SM_WS;    // rows 0..31 = a1-channel weights, [1024..1055] = bias
    float* y_s   = sm + SM_Y;     // [k][12] padded
    float* red_s = sm + SM_RED;
    float* a1_s  = sm + SM_A1;
    float* bb_s  = sm + SM_BB;    // [buf][bank][tt][k]

    int n = blockIdx.x >> 5, b = blockIdx.x & 31;
    int tid  = threadIdx.x;
    int ks   = tid >> 5;          // warp id = k-slice
    int lane = tid & 31;          // = o in GEMM phase

    const float* wg = g_w2 + n * (1057 * 32);

    // ---- small weight block to smem ----
    ws_s[tid & 1023] = wg[tid & 1023];                      // rows 0..31 (all threads, dup ok)
    if (tid < 32) ws_s[1024 + tid] = wg[1056 * 32 + tid];   // bias row

    // ---- register-resident W slice: W[32+ks*32+j][lane] ----
    float wreg[32];
    {
        const float* wp = wg + (32 + ks * 32) * 32 + lane;
#pragma unroll
        for (int j = 0; j < 32; j++) wreg[j] = wp[j * 32];
    }

    // ---- scan lane setup: thread = k = tid ----
    int k = tid;
    int c = ks;
    unsigned sctr = (unsigned)((k * 4 + n) * 32 + b);
    float s1 = tf_uniform(kk.v[10], kk.v[11], sctr);
    float s2 = tf_uniform(kk.v[18], kk.v[19], sctr);
    const float* xbase = g_a1s + (((n * 32 + b) * 32) + c) * 256;  // [n][b][c][t]
    const float* bet1  = g_beta1 + n * 256 * 1024;
    const float* bet2  = g_beta2 + n * 256 * 1024;

    uint32_t bb_base = (uint32_t)__cvta_generic_to_shared(bb_s);

    // ---- prefetch chunk 0 betas (64KB): 4x 16B per thread ----
    {
        int q = tid;  // quad index 0..1023 ; each bank has 2048 quads (8192 floats)
        cp16(bb_base + (0 * 16384 + 0 * 8192) * 4 + q * 16,        bet1 + 0 * 1024 + q * 4);
        cp16(bb_base + (0 * 16384 + 0 * 8192 + 4096) * 4 + q * 16, bet1 + 0 * 1024 + 4096 + q * 4);
        cp16(bb_base + (0 * 16384 + 1 * 8192) * 4 + q * 16,        bet2 + 0 * 1024 + q * 4);
        cp16(bb_base + (0 * 16384 + 1 * 8192 + 4096) * 4 + q * 16, bet2 + 0 * 1024 + 4096 + q * 4);
        cp_commit();
    }

    // ---- reduce map (tid < 256) ----
    int rt = tid >> 5, ro = tid & 31;

    cp_wait0();
    __syncthreads();

    for (int ch = 0; ch < 32; ch++) {
        int t0 = ch * 8;
        int buf = ch & 1;

        // ---- issue prefetch for chunk ch+1 (no wait) ----
        if (ch < 31) {
            int nb = buf ^ 1;
            int tn = (ch + 1) * 8;
            int q = tid;
            uint32_t dst = bb_base + nb * 16384 * 4;
            cp16(dst + q * 16,                 bet1 + tn * 1024 + q * 4);
            cp16(dst + 4096 * 4 + q * 16,      bet1 + tn * 1024 + 4096 + q * 4);
            cp16(dst + 8192 * 4 + q * 16,      bet2 + tn * 1024 + q * 4);
            cp16(dst + 12288 * 4 + q * 16,     bet2 + tn * 1024 + 4096 + q * 4);
            cp_commit();
        }

        // ===== scan 8 steps from smem betas =====
        const float* bbp = bb_s + buf * 16384;
        float yv[8];
#pragma unroll
        for (int tt = 0; tt < 8; tt++) {
            float b1 = bbp[tt * 1024 + k];
            float b2 = bbp[8192 + tt * 1024 + k];
            float xv = xbase[t0 + tt];
            if (lane == 0) a1_s[tt * 32 + c] = xv;
            float y1 = s1;
            s1 = b1 * s1 + (1.0f - b1) * xv;
            yv[tt] = s2;                        // pre-update output
            s2 = b2 * s2 + (1.0f - b2) * y1;
        }
        *(float4*)(y_s + k * 12)     = make_float4(yv[0], yv[1], yv[2], yv[3]);
        *(float4*)(y_s + k * 12 + 4) = make_float4(yv[4], yv[5], yv[6], yv[7]);
        __syncthreads();

        // ===== GEMM (packed f32x2): lane=o, 8 t, 32-k slice =====
        unsigned long long a01 = 0ull, a23 = 0ull, a45 = 0ull, a67 = 0ull;
        const float* yrow = y_s + ks * 32 * 12;
#pragma unroll
        for (int j = 0; j < 32; j++) {
            ulonglong2 u0 = *(const ulonglong2*)(yrow + j * 12);       // t0t1 | t2t3
            ulonglong2 u1 = *(const ulonglong2*)(yrow + j * 12 + 4);   // t4t5 | t6t7
            unsigned long long wp2;
            asm("mov.b64 %0, {%1, %1};" : "=l"(wp2) : "f"(wreg[j]));
            asm("fma.rn.f32x2 %0, %1, %2, %0;" : "+l"(a01) : "l"(wp2), "l"(u0.x));
            asm("fma.rn.f32x2 %0, %1, %2, %0;" : "+l"(a23) : "l"(wp2), "l"(u0.y));
            asm("fma.rn.f32x2 %0, %1, %2, %0;" : "+l"(a45) : "l"(wp2), "l"(u1.x));
            asm("fma.rn.f32x2 %0, %1, %2, %0;" : "+l"(a67) : "l"(wp2), "l"(u1.y));
        }
        {
            float v0, v1;
            asm("mov.b64 {%0, %1}, %2;" : "=f"(v0), "=f"(v1) : "l"(a01));
            red_s[(0 * 32 + ks) * 33 + lane] = v0;
            red_s[(1 * 32 + ks) * 33 + lane] = v1;
            asm("mov.b64 {%0, %1}, %2;" : "=f"(v0), "=f"(v1) : "l"(a23));
            red_s[(2 * 32 + ks) * 33 + lane] = v0;
            red_s[(3 * 32 + ks) * 33 + lane] = v1;
            asm("mov.b64 {%0, %1}, %2;" : "=f"(v0), "=f"(v1) : "l"(a45));
            red_s[(4 * 32 + ks) * 33 + lane] = v0;
            red_s[(5 * 32 + ks) * 33 + lane] = v1;
            asm("mov.b64 {%0, %1}, %2;" : "=f"(v0), "=f"(v1) : "l"(a67));
            red_s[(6 * 32 + ks) * 33 + lane] = v0;
            red_s[(7 * 32 + ks) * 33 + lane] = v1;
        }
        __syncthreads();

        // ===== reduce + a1 term + bias + act + store =====
        if (tid < 256) {
            float z0 = ws_s[1024 + ro];          // bias
            float z1 = 0.f, z2 = 0.f, z3 = 0.f;
#pragma unroll
            for (int j = 0; j < 32; j += 4) {
                z0 += red_s[(rt * 32 + j + 0) * 33 + ro];
                z1 += red_s[(rt * 32 + j + 1) * 33 + ro];
                z2 += red_s[(rt * 32 + j + 2) * 33 + ro];
                z3 += red_s[(rt * 32 + j + 3) * 33 + ro];
            }
#pragma unroll
            for (int cc = 0; cc < 32; cc += 4) {
                z0 = fmaf(ws_s[(cc + 0) * 32 + ro], a1_s[rt * 32 + cc + 0], z0);
                z1 = fmaf(ws_s[(cc + 1) * 32 + ro], a1_s[rt * 32 + cc + 1], z1);
                z2 = fmaf(ws_s[(cc + 2) * 32 + ro], a1_s[rt * 32 + cc + 2], z2);
                z3 = fmaf(ws_s[(cc + 3) * 32 + ro], a1_s[rt * 32 + cc + 3], z3);
            }
            float z = (z0 + z1) + (z2 + z3);
            float a = 0.05f + 0.5f * tanhf((z - 0.3f) * 3.0f);
            out[((n * 32 + b) * 32 + ro) * 256 + t0 + rt] = a;
        }
        cp_wait0();
        __syncthreads();
    }
}

// ---------------- host-side threefry for key derivation ----------------
static void h_tf2x32(unsigned k0, unsigned k1, unsigned x0, unsigned x1,
                     unsigned& o0, unsigned& o1) {
    unsigned ks2 = k0 ^ k1 ^ 0x1BD11BDAu;
    x0 += k0; x1 += k1;
#define HTFR(r) { x0 += x1; x1 = (x1 << (r)) | (x1 >> (32 - (r))); x1 ^= x0; }
    HTFR(13) HTFR(15) HTFR(26) HTFR(6)
    x0 += k1; x1 += ks2 + 1u;
    HTFR(17) HTFR(29) HTFR(16) HTFR(24)
    x0 += ks2; x1 += k0 + 2u;
    HTFR(13) HTFR(15) HTFR(26) HTFR(6)
    x0 += k0; x1 += k1 + 3u;
    HTFR(17) HTFR(29) HTFR(16) HTFR(24)
    x0 += k1; x1 += ks2 + 4u;
    HTFR(13) HTFR(15) HTFR(26) HTFR(6)
    x0 += ks2; x1 += k0 + 5u;
#undef HTFR
    o0 = x0; o1 = x1;
}

// ---------------- launch ----------------
extern "C" void kernel_launch(void* const* d_in, const int* in_sizes, int n_in,
                              void* d_out, int out_size) {
    (void)in_sizes; (void)n_in; (void)out_size;
    const float* x      = (const float*)d_in[0];   // (4,32,32,256)
    const float* theta1 = (const float*)d_in[1];   // (34,32)
    const float* theta2 = (const float*)d_in[2];   // (1058,32)
    const float* Rlf    = (const float*)d_in[3];   // (32,32,2)
    const float* Clf    = (const float*)d_in[4];   // (32,32,2)
    float* out = (float*)d_out;

    Keys kk;
    unsigned ck[8];
    for (int i = 0; i < 4; i++) h_tf2x32(0u, 42u, 0u, (unsigned)i, ck[2 * i], ck[2 * i + 1]);
    kk.v[0] = ck[0]; kk.v[1] = ck[1];   // k1 (pmac1 noise)
    kk.v[2] = ck[6]; kk.v[3] = ck[7];   // k4 (pmac2 noise)
    for (int bank = 0; bank < 2; bank++) {
        unsigned b0 = ck[2 + 2 * bank], b1 = ck[3 + 2 * bank];  // k2 / k3
        for (int j = 0; j < 4; j++)
            h_tf2x32(b0, b1, 0u, (unsigned)j,
                     kk.v[4 + bank * 8 + 2 * j], kk.v[4 + bank * 8 + 2 * j + 1]);
    }

    static int smem_set = 0;
    if (!smem_set) {
        cudaFuncSetAttribute(k_fused, cudaFuncAttributeMaxDynamicSharedMemorySize,
                             SM_TOT * sizeof(float));
        smem_set = 1;
    }

    k_A<<<8448, 256>>>(kk, x, theta1, theta2, Rlf, Clf);
    k_fused<<<128, 1024, SM_TOT * sizeof(float)>>>(kk, out);
}